// round 2
// baseline (speedup 1.0000x reference)
#include <cuda_runtime.h>
#include <math.h>

// Problem constants: L=K=KB=512, B=1, BATCH=16, C=2L=1024
#define BATCH 16
#define D 512            // L == K == KB
#define C2 1024          // conv channels (2L)
#define K3 3072          // conv GEMM K = 1024 channels * 3 taps

// ---------------- scratch (device globals; no allocation) ----------------
__device__ float g_Xe[BATCH * D * D];
__device__ float g_Se[BATCH * D * D];
__device__ float g_Ax[BATCH * D * D];
__device__ float g_As[BATCH * D * D];
__device__ float g_Xa[BATCH * D * D];
__device__ float g_Sa[BATCH * D * D];
__device__ float g_Mx[BATCH * D * D];
__device__ float g_Ms[BATCH * D * D];
__device__ float g_Xh[BATCH * C2 * D];
__device__ float g_Sh[BATCH * C2 * D];
__device__ float g_Wpx[K3 * C2];
__device__ float g_Wps[K3 * C2];

// ---------------- 512x512x512 SGEMM, 128x128 tile, 8x8 per thread ----------------
// C[b] = op(A[b]) @ B[b]; TRANSA: C = A^T B with A stored (K x M) row-major.
template<bool TRANSA>
__global__ __launch_bounds__(256, 2)
void sgemm512(const float* __restrict__ A, const float* __restrict__ B,
              float* __restrict__ Cm,
              long long sA, long long sB, long long sC)
{
    const int bM = blockIdx.y * 128;
    const int bN = blockIdx.x * 128;
    A += (long long)blockIdx.z * sA;
    B += (long long)blockIdx.z * sB;
    Cm += (long long)blockIdx.z * sC;

    __shared__ float As[8][128];
    __shared__ float Bs[8][128];

    const int tid = threadIdx.x;
    const int tr = tid >> 4;     // 0..15
    const int tc = tid & 15;     // 0..15

    float acc[8][8];
#pragma unroll
    for (int i = 0; i < 8; i++)
#pragma unroll
        for (int j = 0; j < 8; j++) acc[i][j] = 0.f;

    for (int k0 = 0; k0 < D; k0 += 8) {
        if (TRANSA) {
            const int kk = tid >> 5, m4 = (tid & 31) * 4;
            *(float4*)&As[kk][m4] = *(const float4*)&A[(long long)(k0 + kk) * D + bM + m4];
        } else {
            const int row = tid >> 1, seg = (tid & 1) * 4;
            const float4 v = *(const float4*)&A[(long long)(bM + row) * D + k0 + seg];
            As[seg + 0][row] = v.x; As[seg + 1][row] = v.y;
            As[seg + 2][row] = v.z; As[seg + 3][row] = v.w;
        }
        {
            const int kk = tid >> 5, n4 = (tid & 31) * 4;
            *(float4*)&Bs[kk][n4] = *(const float4*)&B[(long long)(k0 + kk) * D + bN + n4];
        }
        __syncthreads();
#pragma unroll
        for (int kk = 0; kk < 8; kk++) {
            float a[8], bb[8];
            *(float4*)&a[0]  = *(float4*)&As[kk][tr * 8];
            *(float4*)&a[4]  = *(float4*)&As[kk][tr * 8 + 4];
            *(float4*)&bb[0] = *(float4*)&Bs[kk][tc * 8];
            *(float4*)&bb[4] = *(float4*)&Bs[kk][tc * 8 + 4];
#pragma unroll
            for (int i = 0; i < 8; i++)
#pragma unroll
                for (int j = 0; j < 8; j++)
                    acc[i][j] = fmaf(a[i], bb[j], acc[i][j]);
        }
        __syncthreads();
    }

#pragma unroll
    for (int i = 0; i < 8; i++) {
        float* dst = &Cm[(long long)(bM + tr * 8 + i) * D + bN + tc * 8];
        *(float4*)&dst[0] = make_float4(acc[i][0], acc[i][1], acc[i][2], acc[i][3]);
        *(float4*)&dst[4] = make_float4(acc[i][4], acc[i][5], acc[i][6], acc[i][7]);
    }
}

// ---------------- row softmax over 512-wide contiguous rows ----------------
__global__ void softmax_rows(float* __restrict__ G)
{
    float* row = G + (long long)blockIdx.x * D;
    const int t = threadIdx.x;           // 256 threads
    const int lane = t & 31, w = t >> 5; // 8 warps

    float v0 = row[t], v1 = row[t + 256];
    __shared__ float sh[8];

    // max
    float m = fmaxf(v0, v1);
#pragma unroll
    for (int o = 16; o > 0; o >>= 1) m = fmaxf(m, __shfl_xor_sync(0xffffffffu, m, o));
    if (lane == 0) sh[w] = m;
    __syncthreads();
    if (w == 0) {
        float x = (lane < 8) ? sh[lane] : -INFINITY;
#pragma unroll
        for (int o = 4; o > 0; o >>= 1) x = fmaxf(x, __shfl_xor_sync(0xffffffffu, x, o));
        if (lane == 0) sh[0] = x;
    }
    __syncthreads();
    const float M = sh[0];
    __syncthreads();

    // sum
    float e0 = expf(v0 - M), e1 = expf(v1 - M);
    float s = e0 + e1;
#pragma unroll
    for (int o = 16; o > 0; o >>= 1) s += __shfl_xor_sync(0xffffffffu, s, o);
    if (lane == 0) sh[w] = s;
    __syncthreads();
    if (w == 0) {
        float x = (lane < 8) ? sh[lane] : 0.f;
#pragma unroll
        for (int o = 4; o > 0; o >>= 1) x += __shfl_xor_sync(0xffffffffu, x, o);
        if (lane == 0) sh[0] = x;
    }
    __syncthreads();
    const float inv = 1.f / sh[0];

    row[t] = e0 * inv;
    row[t + 256] = e1 * inv;
}

// ---------------- build X_hat / S_hat : (b, 1024, 512) ----------------
// Hat[b,c,k] = (c<512 ? M[b,c,k]*In[b,c,k] : In[b,c-512,k]) (+ sin(k) if addPos)
__global__ void build_hat(const float* __restrict__ Mm, const float* __restrict__ In,
                          float* __restrict__ Hat, int addPos)
{
    long long i = (long long)blockIdx.x * blockDim.x + threadIdx.x;
    const long long total = (long long)BATCH * C2 * D;
    if (i >= total) return;
    int k = (int)(i % D);
    long long r = i / D;
    int c = (int)(r % C2);
    long long b = r / C2;
    long long base = b * D * D + (long long)(c & (D - 1)) * D + k;
    float x = In[base];
    float v = (c < D) ? Mm[base] * x : x;
    if (addPos) v += sinf((float)k);
    Hat[i] = v;
}

// ---------------- pack conv weights: Wp[(i*3+t)*1024 + o] = w[o,i,t,1] ----------------
__global__ void pack_w(const float* __restrict__ w, float* __restrict__ wp)
{
    __shared__ float tile[32][33];
    const int k0 = blockIdx.x * 32;   // k3 = i*3+t, 0..3071
    const int o0 = blockIdx.y * 32;   // o, 0..1023
    const int tx = threadIdx.x, ty = threadIdx.y;  // 32 x 8
#pragma unroll
    for (int r = 0; r < 32; r += 8)
        tile[ty + r][tx] = w[(long long)(o0 + ty + r) * 9216 + (long long)(k0 + tx) * 3 + 1];
    __syncthreads();
#pragma unroll
    for (int r = 0; r < 32; r += 8)
        wp[(long long)(k0 + ty + r) * C2 + o0 + tx] = tile[tx][ty + r];
}

// ---------------- conv as implicit GEMM: Out[o,h] = bias[o] + sum_k3 Wp[k3][o]*In[i][h+t-1]
__global__ __launch_bounds__(256, 2)
void conv3(const float* __restrict__ Wp, const float* __restrict__ In,
           const float* __restrict__ bias, float* __restrict__ Out, int chanOff)
{
    const int bM = blockIdx.y * 128;   // o
    const int bN = blockIdx.x * 128;   // h
    const float* Inb = In + (long long)blockIdx.z * C2 * D;
    float* Outb = Out + (long long)blockIdx.z * 2048 * D + (long long)chanOff * D;

    __shared__ float As[8][128];
    __shared__ float Bs[8][128];

    const int tid = threadIdx.x;
    const int tr = tid >> 4, tc = tid & 15;
    const int kk = tid >> 5, seg4 = (tid & 31) * 4;

    float acc[8][8];
#pragma unroll
    for (int i = 0; i < 8; i++)
#pragma unroll
        for (int j = 0; j < 8; j++) acc[i][j] = 0.f;

    for (int k0 = 0; k0 < K3; k0 += 8) {
        // A: packed weights (coalesced)
        *(float4*)&As[kk][seg4] = *(const float4*)&Wp[(long long)(k0 + kk) * C2 + bM + seg4];
        // B: shifted input rows with zero pad
        {
            const int k3 = k0 + kk;
            const int ci = k3 / 3;
            const int t  = k3 - ci * 3;
            const float* src = Inb + (long long)ci * D;
#pragma unroll
            for (int r = 0; r < 4; r++) {
                const int h = bN + seg4 + r + t - 1;
                Bs[kk][seg4 + r] = (h >= 0 && h < D) ? src[h] : 0.f;
            }
        }
        __syncthreads();
#pragma unroll
        for (int q = 0; q < 8; q++) {
            float a[8], bb[8];
            *(float4*)&a[0]  = *(float4*)&As[q][tr * 8];
            *(float4*)&a[4]  = *(float4*)&As[q][tr * 8 + 4];
            *(float4*)&bb[0] = *(float4*)&Bs[q][tc * 8];
            *(float4*)&bb[4] = *(float4*)&Bs[q][tc * 8 + 4];
#pragma unroll
            for (int i = 0; i < 8; i++)
#pragma unroll
                for (int j = 0; j < 8; j++)
                    acc[i][j] = fmaf(a[i], bb[j], acc[i][j]);
        }
        __syncthreads();
    }

#pragma unroll
    for (int i = 0; i < 8; i++) {
        const float bo = bias[bM + tr * 8 + i];
        float* dst = &Outb[(long long)(bM + tr * 8 + i) * D + bN + tc * 8];
        *(float4*)&dst[0] = make_float4(acc[i][0] + bo, acc[i][1] + bo, acc[i][2] + bo, acc[i][3] + bo);
        *(float4*)&dst[4] = make_float4(acc[i][4] + bo, acc[i][5] + bo, acc[i][6] + bo, acc[i][7] + bo);
    }
}

// ---------------- launcher ----------------
extern "C" void kernel_launch(void* const* d_in, const int* in_sizes, int n_in,
                              void* d_out, int out_size)
{
    const float* X   = (const float*)d_in[0];
    const float* S   = (const float*)d_in[1];
    const float* W1x = (const float*)d_in[2];
    const float* W1s = (const float*)d_in[3];
    const float* W2x = (const float*)d_in[4];
    const float* W2s = (const float*)d_in[5];
    const float* cwx = (const float*)d_in[6];
    const float* cbx = (const float*)d_in[7];
    const float* cws = (const float*)d_in[8];
    const float* cbs = (const float*)d_in[9];
    float* out = (float*)d_out;

    float *Xe, *Se, *Ax, *As_, *Xa, *Sa, *Mx, *Ms, *Xh, *Sh, *Wpx, *Wps;
    cudaGetSymbolAddress((void**)&Xe,  g_Xe);
    cudaGetSymbolAddress((void**)&Se,  g_Se);
    cudaGetSymbolAddress((void**)&Ax,  g_Ax);
    cudaGetSymbolAddress((void**)&As_, g_As);
    cudaGetSymbolAddress((void**)&Xa,  g_Xa);
    cudaGetSymbolAddress((void**)&Sa,  g_Sa);
    cudaGetSymbolAddress((void**)&Mx,  g_Mx);
    cudaGetSymbolAddress((void**)&Ms,  g_Ms);
    cudaGetSymbolAddress((void**)&Xh,  g_Xh);
    cudaGetSymbolAddress((void**)&Sh,  g_Sh);
    cudaGetSymbolAddress((void**)&Wpx, g_Wpx);
    cudaGetSymbolAddress((void**)&Wps, g_Wps);

    const long long sF = (long long)D * D;
    const dim3 gG(4, 4, BATCH);

    // conv weight packing (independent; overlaps nothing but starts the stream)
    pack_w<<<dim3(K3 / 32, C2 / 32), dim3(32, 8)>>>(cwx, Wpx);
    pack_w<<<dim3(K3 / 32, C2 / 32), dim3(32, 8)>>>(cws, Wps);

    // projections (cross-wired): Xe = S@W1x, Se = X@W1s
    sgemm512<false><<<gG, 256>>>(S, W1x, Xe, sF, 0, sF);
    sgemm512<false><<<gG, 256>>>(X, W1s, Se, sF, 0, sF);

    // Gram matrices + softmax
    sgemm512<true><<<gG, 256>>>(Xe, Xe, Ax,  sF, sF, sF);
    sgemm512<true><<<gG, 256>>>(Se, Se, As_, sF, sF, sF);
    softmax_rows<<<BATCH * D, 256>>>(Ax);
    softmax_rows<<<BATCH * D, 256>>>(As_);

    // attention apply
    sgemm512<false><<<gG, 256>>>(Xe, Ax,  Xa, sF, sF, sF);
    sgemm512<false><<<gG, 256>>>(Se, As_, Sa, sF, sF, sF);

    // mix (B=1 -> plain GEMM with W2)
    sgemm512<false><<<gG, 256>>>(Xa, W2x, Mx, sF, 0, sF);
    sgemm512<false><<<gG, 256>>>(Sa, W2s, Ms, sF, 0, sF);

    // build conv inputs
    const long long totHat = (long long)BATCH * C2 * D;
    build_hat<<<(unsigned)((totHat + 255) / 256), 256>>>(Mx, X, Xh, 0);
    build_hat<<<(unsigned)((totHat + 255) / 256), 256>>>(Ms, S, Sh, 1);

    // convs -> output halves
    conv3<<<dim3(4, 8, BATCH), 256>>>(Wpx, Xh, cbx, out, 0);
    conv3<<<dim3(4, 8, BATCH), 256>>>(Wps, Sh, cbs, out, C2);
}

// round 5
// speedup vs baseline: 2.9140x; 2.9140x over previous
#include <cuda_runtime.h>
#include <cuda_bf16.h>
#include <cstdint>
#include <math.h>

#define BATCH 16
#define D 512
#define C2 1024
typedef __nv_bfloat16 bf16;
#define FRM (BATCH * D * D)
#define HATN (BATCH * D * C2)
#define WKN (3 * C2 * C2)
#define EPSTRIDE 132   // fp32 staging stride: 132*4=528B, 16B-aligned, bank shift 4

// ---------------- scratch (device globals; no allocation) ----------------
__device__ bf16 g_Xsp[2][FRM];
__device__ bf16 g_Ssp[2][FRM];
__device__ bf16 g_W1xT[2][D * D];
__device__ bf16 g_W1sT[2][D * D];
__device__ bf16 g_W2xT[2][D * D];
__device__ bf16 g_W2sT[2][D * D];
__device__ bf16 g_Xe[2][FRM];
__device__ bf16 g_XeT[2][FRM];
__device__ bf16 g_Se[2][FRM];
__device__ bf16 g_SeT[2][FRM];
__device__ float g_Gx[FRM];
__device__ float g_Gs[FRM];
__device__ float g_st[4][BATCH * D];
__device__ bf16 g_AxT[2][FRM];
__device__ bf16 g_AsT[2][FRM];
__device__ bf16 g_Xa[2][FRM];
__device__ bf16 g_Sa[2][FRM];
__device__ float g_Mx[FRM];
__device__ float g_Ms[FRM];
__device__ bf16 g_Hx[2][HATN];
__device__ bf16 g_Hs[2][HATN];
__device__ bf16 g_Wkx[2][WKN];
__device__ bf16 g_Wks[2][WKN];

// ---------------- helpers ----------------
__device__ __forceinline__ uint32_t s2u(const void* p) {
    uint32_t a;
    asm("{ .reg .u64 t; cvta.to.shared.u64 t, %1; cvt.u32.u64 %0, t; }" : "=r"(a) : "l"(p));
    return a;
}
__device__ __forceinline__ void split2(float v, bf16& h, bf16& l) {
    h = __float2bfloat16(v);
    l = __float2bfloat16(v - __bfloat162float(h));
}
__device__ __forceinline__ void ldsm4(uint32_t& r0, uint32_t& r1, uint32_t& r2, uint32_t& r3, uint32_t a) {
    asm volatile("ldmatrix.sync.aligned.m8n8.x4.shared.b16 {%0,%1,%2,%3}, [%4];"
                 : "=r"(r0), "=r"(r1), "=r"(r2), "=r"(r3) : "r"(a));
}
__device__ __forceinline__ void mma16816(float* c, uint32_t a0, uint32_t a1, uint32_t a2, uint32_t a3,
                                         uint32_t b0, uint32_t b1) {
    asm volatile("mma.sync.aligned.m16n8k16.row.col.f32.bf16.bf16.f32 "
                 "{%0,%1,%2,%3},{%4,%5,%6,%7},{%8,%9},{%0,%1,%2,%3};"
                 : "+f"(c[0]), "+f"(c[1]), "+f"(c[2]), "+f"(c[3])
                 : "r"(a0), "r"(a1), "r"(a2), "r"(a3), "r"(b0), "r"(b1));
}
template<int N> __device__ __forceinline__ void cp_wait() {
    asm volatile("cp.async.wait_group %0;" :: "n"(N) : "memory");
}
__device__ __forceinline__ void cp_commit() {
    asm volatile("cp.async.commit_group;" ::: "memory");
}

// load [128 x 64] bf16 K-major tile into SW128 smem via cp.async; zero-fill OOB rows
__device__ __forceinline__ void cp_tile(uint32_t dstbase, const bf16* __restrict__ g,
                                        long long ld, int rowBase, int rowLim, int k0) {
    const int tid = threadIdx.x;
#pragma unroll
    for (int j = 0; j < 4; j++) {
        int u = tid + j * 256;
        int row = u >> 3, c8 = u & 7;
        int gr = rowBase + row;
        int ok = (gr >= 0 && gr < rowLim);
        const void* src = (const void*)(g + (long long)(ok ? gr : 0) * ld + k0 + c8 * 8);
        int bo = row * 128 + c8 * 16;
        uint32_t dst = dstbase + (bo ^ ((bo >> 3) & 0x70));
        int sz = ok ? 16 : 0;
        asm volatile("cp.async.cg.shared.global [%0], [%1], 16, %2;" :: "r"(dst), "l"(src), "r"(sz) : "memory");
    }
}

// one K=64 chunk of HMMA on swizzled smem tiles
__device__ __forceinline__ void compute_chunk(uint32_t smA, uint32_t smB, int wm, int wn, int lane,
                                              float (&c)[4][4][4]) {
#pragma unroll
    for (int ks = 0; ks < 4; ks++) {
        uint32_t a[4][4], b[4][2];
#pragma unroll
        for (int mf = 0; mf < 4; mf++) {
            int m_loc = wm + mf * 16 + (lane & 7) + ((lane >> 3) & 1) * 8;
            int kb = (lane >> 4) * 16;
            uint32_t addr = smA + m_loc * 128 + ((kb + ks * 32) ^ ((m_loc & 7) * 16));
            ldsm4(a[mf][0], a[mf][1], a[mf][2], a[mf][3], addr);
        }
#pragma unroll
        for (int nf2 = 0; nf2 < 2; nf2++) {
            int n_loc = wn + nf2 * 16 + (lane & 7) + (lane >> 4) * 8;
            int kb = ((lane >> 3) & 1) * 16;
            uint32_t addr = smB + n_loc * 128 + ((kb + ks * 32) ^ ((n_loc & 7) * 16));
            uint32_t r0, r1, r2, r3;
            ldsm4(r0, r1, r2, r3, addr);
            b[nf2 * 2][0] = r0; b[nf2 * 2][1] = r1;
            b[nf2 * 2 + 1][0] = r2; b[nf2 * 2 + 1][1] = r3;
        }
#pragma unroll
        for (int mf = 0; mf < 4; mf++)
#pragma unroll
            for (int nf = 0; nf < 4; nf++)
                mma16816(c[mf][nf], a[mf][0], a[mf][1], a[mf][2], a[mf][3], b[nf][0], b[nf][1]);
    }
}

#define SA0 0
#define SA1 16384
#define SB0 32768
#define SB1 49152
#define SM_DYN (128 * EPSTRIDE * 4)   // 67584; main loop uses first 65536

// store accumulators to fp32 smem staging tile [128][EPSTRIDE]
__device__ __forceinline__ void stage_acc(float* smf, int wm, int wn, int lane, float (&c)[4][4][4]) {
    const int tg = lane >> 2, tq = lane & 3;
#pragma unroll
    for (int mf = 0; mf < 4; mf++)
#pragma unroll
        for (int nf = 0; nf < 4; nf++) {
            int m0 = wm + mf * 16 + tg, n0 = wn + nf * 8 + tq * 2;
            smf[m0 * EPSTRIDE + n0] = c[mf][nf][0];
            smf[m0 * EPSTRIDE + n0 + 1] = c[mf][nf][1];
            smf[(m0 + 8) * EPSTRIDE + n0] = c[mf][nf][2];
            smf[(m0 + 8) * EPSTRIDE + n0 + 1] = c[mf][nf][3];
        }
}

// ---------------- split-bf16 3-pass GEMM: C[m,n] = sum_k A[m,k]*B[n,k], 512^3 ----------------
// EPI 0: fp32 natural ; EPI 1: bf16 hi/lo natural ; EPI 2: EPI1 + bf16 hi/lo transposed
template<int EPI>
__global__ __launch_bounds__(256, 2)
void mma_gemm(const bf16* __restrict__ Ah, const bf16* __restrict__ Al, long long sA,
              const bf16* __restrict__ Bh, const bf16* __restrict__ Bl, long long sB,
              float* __restrict__ Fo, bf16* __restrict__ Th, bf16* __restrict__ Tl,
              bf16* __restrict__ Uh, bf16* __restrict__ Ul)
{
    extern __shared__ char sm[];
    const int tid = threadIdx.x, wid = tid >> 5, lane = tid & 31;
    const int bN = blockIdx.x * 128, bM = blockIdx.y * 128, z = blockIdx.z;
    const int wm = (wid >> 2) * 64, wn = (wid & 3) * 32;
    const uint32_t smb = s2u(sm);
    const long long zf = (long long)z * D * D;

    Ah += z * sA; Al += z * sA; Bh += z * sB; Bl += z * sB;

    float c[4][4][4];
#pragma unroll
    for (int i = 0; i < 4; i++)
#pragma unroll
        for (int j = 0; j < 4; j++)
#pragma unroll
            for (int q = 0; q < 4; q++) c[i][j][q] = 0.f;

    cp_tile(smb + SA0, Ah, D, bM, 1 << 30, 0);
    cp_tile(smb + SB0, Bh, D, bN, 1 << 30, 0);
    cp_commit();

    for (int i = 0; i < 24; i++) {
        if (i + 1 < 24) {
            const int j = i + 1, p = j >> 3, k0 = (j & 7) * 64;
            const bf16* Ap = (p < 2) ? Ah : Al;
            const bf16* Bp = (p == 1) ? Bl : Bh;
            cp_tile(smb + ((j & 1) ? SA1 : SA0), Ap, D, bM, 1 << 30, k0);
            cp_tile(smb + ((j & 1) ? SB1 : SB0), Bp, D, bN, 1 << 30, k0);
            cp_commit();
            cp_wait<1>();
        } else {
            cp_wait<0>();
        }
        __syncthreads();
        compute_chunk(smb + ((i & 1) ? SA1 : SA0), smb + ((i & 1) ? SB1 : SB0), wm, wn, lane, c);
        __syncthreads();
    }

    float* smf = (float*)sm;
    stage_acc(smf, wm, wn, lane, c);
    __syncthreads();

    const int r = tid >> 1, hf = tid & 1;
    if (EPI == 0) {
        float* dst = Fo + zf + (long long)(bM + r) * D + bN + hf * 64;
#pragma unroll
        for (int q = 0; q < 16; q++) {
            float4 v = *(float4*)&smf[r * EPSTRIDE + hf * 64 + q * 4];
            *(float4*)&dst[q * 4] = v;
        }
    } else {
        bf16* th = Th + zf + (long long)(bM + r) * D + bN + hf * 64;
        bf16* tl = Tl + zf + (long long)(bM + r) * D + bN + hf * 64;
#pragma unroll
        for (int q = 0; q < 32; q++) {
            float f0 = smf[r * EPSTRIDE + hf * 64 + q * 2];
            float f1 = smf[r * EPSTRIDE + hf * 64 + q * 2 + 1];
            bf16 h0, l0, h1, l1;
            split2(f0, h0, l0); split2(f1, h1, l1);
            __nv_bfloat162 vh; vh.x = h0; vh.y = h1;
            __nv_bfloat162 vl; vl.x = l0; vl.y = l1;
            *(__nv_bfloat162*)(th + q * 2) = vh;
            *(__nv_bfloat162*)(tl + q * 2) = vl;
        }
        if (EPI == 2) {
            const int n = tid >> 1, hm = tid & 1;
            bf16* uh = Uh + zf + (long long)(bN + n) * D + bM + hm * 64;
            bf16* ul = Ul + zf + (long long)(bN + n) * D + bM + hm * 64;
#pragma unroll
            for (int q = 0; q < 32; q++) {
                int m0 = hm * 64 + q * 2;
                float f0 = smf[m0 * EPSTRIDE + n];
                float f1 = smf[(m0 + 1) * EPSTRIDE + n];
                bf16 h0, l0, h1, l1;
                split2(f0, h0, l0); split2(f1, h1, l1);
                __nv_bfloat162 vh; vh.x = h0; vh.y = h1;
                __nv_bfloat162 vl; vl.x = l0; vl.y = l1;
                *(__nv_bfloat162*)(uh + q * 2) = vh;
                *(__nv_bfloat162*)(ul + q * 2) = vl;
            }
        }
    }
}

// ---------------- conv: C[o,h] = bias[o] + sum_{p,t,c} W[t][o][c]*Hat[h+t-1][c] ----------------
__global__ __launch_bounds__(256, 2)
void mma_conv(const bf16* __restrict__ Hh, const bf16* __restrict__ Hl,
              const bf16* __restrict__ Wh, const bf16* __restrict__ Wl,
              const float* __restrict__ bias, float* __restrict__ out, int chanOff)
{
    extern __shared__ char sm[];
    const int tid = threadIdx.x, wid = tid >> 5, lane = tid & 31;
    const int bN = blockIdx.x * 128, bM = blockIdx.y * 128, z = blockIdx.z;
    const int wm = (wid >> 2) * 64, wn = (wid & 3) * 32;
    const uint32_t smb = s2u(sm);

    Hh += (long long)z * D * C2;
    Hl += (long long)z * D * C2;

    float c[4][4][4];
#pragma unroll
    for (int i = 0; i < 4; i++)
#pragma unroll
        for (int j = 0; j < 4; j++)
#pragma unroll
            for (int q = 0; q < 4; q++) c[i][j][q] = 0.f;

    // chunk i: p = i/48, t = (i%48)/16, k0 = (i%16)*64
    cp_tile(smb + SA0, Wh, C2, bM, 1 << 30, 0);
    cp_tile(smb + SB0, Hh, C2, bN - 1, D, 0);
    cp_commit();

    for (int i = 0; i < 144; i++) {
        if (i + 1 < 144) {
            const int j = i + 1;
            const int p = j / 48, rr = j - p * 48;
            const int t = rr >> 4, k0 = (rr & 15) * 64;
            const bf16* Ap = ((p < 2) ? Wh : Wl) + (long long)t * C2 * C2;
            const bf16* Bp = (p == 1) ? Hl : Hh;
            cp_tile(smb + ((j & 1) ? SA1 : SA0), Ap, C2, bM, 1 << 30, k0);
            cp_tile(smb + ((j & 1) ? SB1 : SB0), Bp, C2, bN + t - 1, D, k0);
            cp_commit();
            cp_wait<1>();
        } else {
            cp_wait<0>();
        }
        __syncthreads();
        compute_chunk(smb + ((i & 1) ? SA1 : SA0), smb + ((i & 1) ? SB1 : SB0), wm, wn, lane, c);
        __syncthreads();
    }

    float* smf = (float*)sm;
    stage_acc(smf, wm, wn, lane, c);
    __syncthreads();

    const int r = tid >> 1, hf = tid & 1;
    const int o = bM + r;
    const float bo = __ldg(&bias[o]);
    float* dst = out + ((long long)z * 2048 + chanOff + o) * D + bN + hf * 64;
#pragma unroll
    for (int q = 0; q < 16; q++) {
        float4 v = *(float4*)&smf[r * EPSTRIDE + hf * 64 + q * 4];
        v.x += bo; v.y += bo; v.z += bo; v.w += bo;
        *(float4*)&dst[q * 4] = v;
    }
}

// ---------------- aux kernels ----------------
__global__ void conv_hl(const float* __restrict__ in, bf16* __restrict__ oh,
                        bf16* __restrict__ ol, long long n)
{
    long long i = (long long)blockIdx.x * blockDim.x + threadIdx.x;
    if (i >= n) return;
    bf16 h, l;
    split2(in[i], h, l);
    oh[i] = h; ol[i] = l;
}

__global__ void tr_w(const float* __restrict__ W, bf16* __restrict__ th, bf16* __restrict__ tl)
{
    __shared__ float t[32][33];
    const int j0 = blockIdx.x * 32, k0 = blockIdx.y * 32;
    const int tx = threadIdx.x, ty = threadIdx.y;
#pragma unroll
    for (int r = 0; r < 32; r += 8)
        t[ty + r][tx] = W[(long long)(k0 + ty + r) * D + j0 + tx];
    __syncthreads();
#pragma unroll
    for (int r = 0; r < 32; r += 8) {
        bf16 h, l;
        split2(t[tx][ty + r], h, l);
        long long o = (long long)(j0 + ty + r) * D + k0 + tx;
        th[o] = h; tl[o] = l;
    }
}

__global__ void g_stats(const float* __restrict__ G, float* __restrict__ Mo, float* __restrict__ Ro)
{
    const float* row = G + (long long)blockIdx.x * D;
    const int t = threadIdx.x, lane = t & 31, w = t >> 5;
    float v0 = row[t], v1 = row[t + 256];
    __shared__ float sh[8];
    float m = fmaxf(v0, v1);
#pragma unroll
    for (int o = 16; o > 0; o >>= 1) m = fmaxf(m, __shfl_xor_sync(~0u, m, o));
    if (lane == 0) sh[w] = m;
    __syncthreads();
    if (w == 0) {
        float x = (lane < 8) ? sh[lane] : -INFINITY;
#pragma unroll
        for (int o = 4; o > 0; o >>= 1) x = fmaxf(x, __shfl_xor_sync(~0u, x, o));
        if (lane == 0) sh[0] = x;
    }
    __syncthreads();
    const float M = sh[0];
    __syncthreads();
    float s = expf(v0 - M) + expf(v1 - M);
#pragma unroll
    for (int o = 16; o > 0; o >>= 1) s += __shfl_xor_sync(~0u, s, o);
    if (lane == 0) sh[w] = s;
    __syncthreads();
    if (w == 0) {
        float x = (lane < 8) ? sh[lane] : 0.f;
#pragma unroll
        for (int o = 4; o > 0; o >>= 1) x += __shfl_xor_sync(~0u, x, o);
        if (lane == 0) { Mo[blockIdx.x] = M; Ro[blockIdx.x] = 1.f / x; }
    }
}

// AxT[z][j][i] = exp(G[z][j][i] - m[i]) * r[i]   (uses G symmetry)
__global__ void build_axt(const float* __restrict__ G, const float* __restrict__ Ms,
                          const float* __restrict__ Rs, bf16* __restrict__ th, bf16* __restrict__ tl)
{
    long long idx = (long long)blockIdx.x * blockDim.x + threadIdx.x;
    if (idx >= (long long)FRM) return;
    int i = (int)(idx & (D - 1));
    long long z = idx >> 18;
    float v = expf(G[idx] - __ldg(&Ms[z * D + i])) * __ldg(&Rs[z * D + i]);
    bf16 h, l;
    split2(v, h, l);
    th[idx] = h; tl[idx] = l;
}

// Hat[z][h][c] = Mx[c][h]*X[c][h] (+pe) ; Hat[z][h][c+512] = X[c][h] (+pe)
__global__ void build_hatT(const float* __restrict__ X, const float* __restrict__ Mx,
                           bf16* __restrict__ Hh, bf16* __restrict__ Hl, int addPos)
{
    __shared__ float xs[32][33];
    __shared__ float ms[32][33];
    const int c0 = blockIdx.x * 32, h0 = blockIdx.y * 32, z = blockIdx.z;
    const int tx = threadIdx.x, ty = threadIdx.y;
    const long long zf = (long long)z * D * D;
    const long long zh = (long long)z * D * C2;
#pragma unroll
    for (int r = 0; r < 32; r += 8) {
        xs[ty + r][tx] = X[zf + (long long)(c0 + ty + r) * D + h0 + tx];
        ms[ty + r][tx] = Mx[zf + (long long)(c0 + ty + r) * D + h0 + tx];
    }
    __syncthreads();
#pragma unroll
    for (int r = 0; r < 32; r += 8) {
        const int h = h0 + ty + r, c = c0 + tx;
        const float pe = addPos ? sinf((float)h) : 0.f;
        const float xv = xs[tx][ty + r];
        const float mv = ms[tx][ty + r];
        bf16 hh, ll;
        long long o = zh + (long long)h * C2 + c;
        split2(mv * xv + pe, hh, ll);
        Hh[o] = hh; Hl[o] = ll;
        split2(xv + pe, hh, ll);
        Hh[o + D] = hh; Hl[o + D] = ll;
    }
}

// Wk[t][o][i] = w[o][i][t][1], hi/lo planes
__global__ void pack_w_hl(const float* __restrict__ w, bf16* __restrict__ wh, bf16* __restrict__ wl)
{
    long long idx = (long long)blockIdx.x * blockDim.x + threadIdx.x;
    if (idx >= (long long)WKN) return;
    int i = (int)(idx & (C2 - 1));
    int o = (int)((idx >> 10) & (C2 - 1));
    int t = (int)(idx >> 20);
    bf16 h, l;
    split2(w[(long long)o * 9216 + (long long)i * 9 + t * 3 + 1], h, l);
    wh[idx] = h; wl[idx] = l;
}

// ---------------- launcher ----------------
extern "C" void kernel_launch(void* const* d_in, const int* in_sizes, int n_in,
                              void* d_out, int out_size)
{
    const float* X   = (const float*)d_in[0];
    const float* S   = (const float*)d_in[1];
    const float* W1x = (const float*)d_in[2];
    const float* W1s = (const float*)d_in[3];
    const float* W2x = (const float*)d_in[4];
    const float* W2s = (const float*)d_in[5];
    const float* cwx = (const float*)d_in[6];
    const float* cbx = (const float*)d_in[7];
    const float* cws = (const float*)d_in[8];
    const float* cbs = (const float*)d_in[9];
    float* out = (float*)d_out;

    bf16 *Xsp, *Ssp, *W1xT, *W1sT, *W2xT, *W2sT, *Xe, *XeT, *Se, *SeT;
    bf16 *AxT, *AsT, *Xa, *Sa, *Hx, *Hs, *Wkx, *Wks;
    float *Gx, *Gs, *st, *Mx, *Ms;
    cudaGetSymbolAddress((void**)&Xsp, g_Xsp);   cudaGetSymbolAddress((void**)&Ssp, g_Ssp);
    cudaGetSymbolAddress((void**)&W1xT, g_W1xT); cudaGetSymbolAddress((void**)&W1sT, g_W1sT);
    cudaGetSymbolAddress((void**)&W2xT, g_W2xT); cudaGetSymbolAddress((void**)&W2sT, g_W2sT);
    cudaGetSymbolAddress((void**)&Xe, g_Xe);     cudaGetSymbolAddress((void**)&XeT, g_XeT);
    cudaGetSymbolAddress((void**)&Se, g_Se);     cudaGetSymbolAddress((void**)&SeT, g_SeT);
    cudaGetSymbolAddress((void**)&Gx, g_Gx);     cudaGetSymbolAddress((void**)&Gs, g_Gs);
    cudaGetSymbolAddress((void**)&st, g_st);
    cudaGetSymbolAddress((void**)&AxT, g_AxT);   cudaGetSymbolAddress((void**)&AsT, g_AsT);
    cudaGetSymbolAddress((void**)&Xa, g_Xa);     cudaGetSymbolAddress((void**)&Sa, g_Sa);
    cudaGetSymbolAddress((void**)&Mx, g_Mx);     cudaGetSymbolAddress((void**)&Ms, g_Ms);
    cudaGetSymbolAddress((void**)&Hx, g_Hx);     cudaGetSymbolAddress((void**)&Hs, g_Hs);
    cudaGetSymbolAddress((void**)&Wkx, g_Wkx);   cudaGetSymbolAddress((void**)&Wks, g_Wks);

    cudaFuncSetAttribute(mma_gemm<0>, cudaFuncAttributeMaxDynamicSharedMemorySize, SM_DYN);
    cudaFuncSetAttribute(mma_gemm<1>, cudaFuncAttributeMaxDynamicSharedMemorySize, SM_DYN);
    cudaFuncSetAttribute(mma_gemm<2>, cudaFuncAttributeMaxDynamicSharedMemorySize, SM_DYN);
    cudaFuncSetAttribute(mma_conv,    cudaFuncAttributeMaxDynamicSharedMemorySize, SM_DYN);

    const long long sF = (long long)D * D;
    const long long wofs = (long long)D * D;
    const long long fofs = (long long)FRM;
    const long long hofs = (long long)HATN;
    const long long kofs = (long long)WKN;
    const dim3 gG(4, 4, BATCH);
    const dim3 gC(4, 8, BATCH);

    // prep
    tr_w<<<dim3(16, 16), dim3(32, 8)>>>(W1x, W1xT, W1xT + wofs);
    tr_w<<<dim3(16, 16), dim3(32, 8)>>>(W1s, W1sT, W1sT + wofs);
    tr_w<<<dim3(16, 16), dim3(32, 8)>>>(W2x, W2xT, W2xT + wofs);
    tr_w<<<dim3(16, 16), dim3(32, 8)>>>(W2s, W2sT, W2sT + wofs);
    conv_hl<<<(FRM + 255) / 256, 256>>>(X, Xsp, Xsp + fofs, FRM);
    conv_hl<<<(FRM + 255) / 256, 256>>>(S, Ssp, Ssp + fofs, FRM);
    pack_w_hl<<<(WKN + 255) / 256, 256>>>(cwx, Wkx, Wkx + kofs);
    pack_w_hl<<<(WKN + 255) / 256, 256>>>(cws, Wks, Wks + kofs);

    // Xe = S@W1x (cross-wired), dual natural+transposed bf16 outputs
    mma_gemm<2><<<gG, 256, SM_DYN>>>(Ssp, Ssp + fofs, sF, W1xT, W1xT + wofs, 0,
                                     nullptr, Xe, Xe + fofs, XeT, XeT + fofs);
    mma_gemm<2><<<gG, 256, SM_DYN>>>(Xsp, Xsp + fofs, sF, W1sT, W1sT + wofs, 0,
                                     nullptr, Se, Se + fofs, SeT, SeT + fofs);

    // Gram: G[i][j] = sum_l XeT[i][l]*XeT[j][l]
    mma_gemm<0><<<gG, 256, SM_DYN>>>(XeT, XeT + fofs, sF, XeT, XeT + fofs, sF,
                                     Gx, nullptr, nullptr, nullptr, nullptr);
    mma_gemm<0><<<gG, 256, SM_DYN>>>(SeT, SeT + fofs, sF, SeT, SeT + fofs, sF,
                                     Gs, nullptr, nullptr, nullptr, nullptr);

    // softmax stats + transposed attention matrices
    g_stats<<<BATCH * D, 256>>>(Gx, st + 0 * BATCH * D, st + 1 * BATCH * D);
    g_stats<<<BATCH * D, 256>>>(Gs, st + 2 * BATCH * D, st + 3 * BATCH * D);
    build_axt<<<(FRM + 255) / 256, 256>>>(Gx, st + 0 * BATCH * D, st + 1 * BATCH * D, AxT, AxT + fofs);
    build_axt<<<(FRM + 255) / 256, 256>>>(Gs, st + 2 * BATCH * D, st + 3 * BATCH * D, AsT, AsT + fofs);

    // Xa[l][j] = sum_i Xe[l][i]*AxT[j][i]
    mma_gemm<1><<<gG, 256, SM_DYN>>>(Xe, Xe + fofs, sF, AxT, AxT + fofs, sF,
                                     nullptr, Xa, Xa + fofs, nullptr, nullptr);
    mma_gemm<1><<<gG, 256, SM_DYN>>>(Se, Se + fofs, sF, AsT, AsT + fofs, sF,
                                     nullptr, Sa, Sa + fofs, nullptr, nullptr);

    // Mx[l][j] = sum_k Xa[l][k]*W2xT[j][k]  (fp32 out)
    mma_gemm<0><<<gG, 256, SM_DYN>>>(Xa, Xa + fofs, sF, W2xT, W2xT + wofs, 0,
                                     Mx, nullptr, nullptr, nullptr, nullptr);
    mma_gemm<0><<<gG, 256, SM_DYN>>>(Sa, Sa + fofs, sF, W2sT, W2sT + wofs, 0,
                                     Ms, nullptr, nullptr, nullptr, nullptr);

    // conv inputs (channel-contiguous) and convs
    build_hatT<<<dim3(16, 16, BATCH), dim3(32, 8)>>>(X, Mx, Hx, Hx + hofs, 0);
    build_hatT<<<dim3(16, 16, BATCH), dim3(32, 8)>>>(S, Ms, Hs, Hs + hofs, 1);

    mma_conv<<<gC, 256, SM_DYN>>>(Hx, Hx + hofs, Wkx, Wkx + kofs, cbx, out, 0);
    mma_conv<<<gC, 256, SM_DYN>>>(Hs, Hs + hofs, Wks, Wks + kofs, cbs, out, C2);
}

// round 6
// speedup vs baseline: 3.2013x; 1.0986x over previous
#include <cuda_runtime.h>
#include <cuda_bf16.h>
#include <cstdint>
#include <math.h>

#define BATCH 16
#define D 512
#define C2 1024
typedef __nv_bfloat16 bf16;
#define FRM (BATCH * D * D)
#define HATN (BATCH * D * C2)
#define WKN (3 * C2 * C2)
#define EPSTRIDE 132
#define STAGE_BYTES 32768
#define SM_DYN (3 * STAGE_BYTES)   // 98304: 3 pipeline stages; epilogue reuses

// ---------------- scratch ----------------
__device__ bf16 g_Xsp[2][FRM];
__device__ bf16 g_Ssp[2][FRM];
__device__ bf16 g_W1xT[2][D * D];
__device__ bf16 g_W1sT[2][D * D];
__device__ bf16 g_W2xT[2][D * D];
__device__ bf16 g_W2sT[2][D * D];
__device__ bf16 g_Xe[2][FRM];
__device__ bf16 g_XeT[2][FRM];
__device__ bf16 g_Se[2][FRM];
__device__ bf16 g_SeT[2][FRM];
__device__ float g_Gx[FRM];
__device__ float g_Gs[FRM];
__device__ float g_st[4][BATCH * D];
__device__ bf16 g_AxT[2][FRM];
__device__ bf16 g_AsT[2][FRM];
__device__ bf16 g_Xa[2][FRM];
__device__ bf16 g_Sa[2][FRM];
__device__ float g_Mx[FRM];
__device__ float g_Ms[FRM];
__device__ bf16 g_Hx[2][HATN];
__device__ bf16 g_Hs[2][HATN];
__device__ bf16 g_Wkx[2][WKN];
__device__ bf16 g_Wks[2][WKN];

// ---------------- param structs ----------------
struct GemmSet {
    const bf16 *Ah, *Al, *Bh, *Bl;
    float* Fo;
    bf16 *Th, *Tl, *Uh, *Ul;
};
struct GemmPair { GemmSet s[2]; };
struct ConvSet {
    const bf16 *Hh, *Hl, *Wh, *Wl;
    const float* bias;
    int chanOff;
};
struct ConvPair { ConvSet s[2]; };

// ---------------- helpers ----------------
__device__ __forceinline__ uint32_t s2u(const void* p) {
    uint32_t a;
    asm("{ .reg .u64 t; cvta.to.shared.u64 t, %1; cvt.u32.u64 %0, t; }" : "=r"(a) : "l"(p));
    return a;
}
__device__ __forceinline__ void split2(float v, bf16& h, bf16& l) {
    h = __float2bfloat16(v);
    l = __float2bfloat16(v - __bfloat162float(h));
}
__device__ __forceinline__ void ldsm4(uint32_t& r0, uint32_t& r1, uint32_t& r2, uint32_t& r3, uint32_t a) {
    asm volatile("ldmatrix.sync.aligned.m8n8.x4.shared.b16 {%0,%1,%2,%3}, [%4];"
                 : "=r"(r0), "=r"(r1), "=r"(r2), "=r"(r3) : "r"(a));
}
__device__ __forceinline__ void mma16816(float* c, uint32_t a0, uint32_t a1, uint32_t a2, uint32_t a3,
                                         uint32_t b0, uint32_t b1) {
    asm volatile("mma.sync.aligned.m16n8k16.row.col.f32.bf16.bf16.f32 "
                 "{%0,%1,%2,%3},{%4,%5,%6,%7},{%8,%9},{%0,%1,%2,%3};"
                 : "+f"(c[0]), "+f"(c[1]), "+f"(c[2]), "+f"(c[3])
                 : "r"(a0), "r"(a1), "r"(a2), "r"(a3), "r"(b0), "r"(b1));
}
template<int N> __device__ __forceinline__ void cp_wait() {
    asm volatile("cp.async.wait_group %0;" :: "n"(N) : "memory");
}
__device__ __forceinline__ void cp_commit() {
    asm volatile("cp.async.commit_group;" ::: "memory");
}

// [128 x 64] bf16 K-major tile -> SW128 smem via cp.async, zero-fill OOB rows
__device__ __forceinline__ void cp_tile(uint32_t dstbase, const bf16* __restrict__ g,
                                        long long ld, int rowBase, int rowLim, int k0) {
    const int tid = threadIdx.x;
#pragma unroll
    for (int j = 0; j < 4; j++) {
        int u = tid + j * 256;
        int row = u >> 3, c8 = u & 7;
        int gr = rowBase + row;
        int ok = (gr >= 0 && gr < rowLim);
        const void* src = (const void*)(g + (long long)(ok ? gr : 0) * ld + k0 + c8 * 8);
        int bo = row * 128 + c8 * 16;
        uint32_t dst = dstbase + (bo ^ ((bo >> 3) & 0x70));
        int sz = ok ? 16 : 0;
        asm volatile("cp.async.cg.shared.global [%0], [%1], 16, %2;" :: "r"(dst), "l"(src), "r"(sz) : "memory");
    }
}

// one K=64 chunk of HMMA
__device__ __forceinline__ void compute_chunk(uint32_t smA, uint32_t smB, int wm, int wn, int lane,
                                              float (&c)[4][4][4]) {
#pragma unroll
    for (int ks = 0; ks < 4; ks++) {
        uint32_t a[4][4], b[4][2];
#pragma unroll
        for (int mf = 0; mf < 4; mf++) {
            int m_loc = wm + mf * 16 + (lane & 7) + ((lane >> 3) & 1) * 8;
            int kb = (lane >> 4) * 16;
            uint32_t addr = smA + m_loc * 128 + ((kb + ks * 32) ^ ((m_loc & 7) * 16));
            ldsm4(a[mf][0], a[mf][1], a[mf][2], a[mf][3], addr);
        }
#pragma unroll
        for (int nf2 = 0; nf2 < 2; nf2++) {
            int n_loc = wn + nf2 * 16 + (lane & 7) + (lane >> 4) * 8;
            int kb = ((lane >> 3) & 1) * 16;
            uint32_t addr = smB + n_loc * 128 + ((kb + ks * 32) ^ ((n_loc & 7) * 16));
            uint32_t r0, r1, r2, r3;
            ldsm4(r0, r1, r2, r3, addr);
            b[nf2 * 2][0] = r0; b[nf2 * 2][1] = r1;
            b[nf2 * 2 + 1][0] = r2; b[nf2 * 2 + 1][1] = r3;
        }
#pragma unroll
        for (int mf = 0; mf < 4; mf++)
#pragma unroll
            for (int nf = 0; nf < 4; nf++)
                mma16816(c[mf][nf], a[mf][0], a[mf][1], a[mf][2], a[mf][3], b[nf][0], b[nf][1]);
    }
}

__device__ __forceinline__ void stage_acc(float* smf, int wm, int wn, int lane, float (&c)[4][4][4]) {
    const int tg = lane >> 2, tq = lane & 3;
#pragma unroll
    for (int mf = 0; mf < 4; mf++)
#pragma unroll
        for (int nf = 0; nf < 4; nf++) {
            int m0 = wm + mf * 16 + tg, n0 = wn + nf * 8 + tq * 2;
            smf[m0 * EPSTRIDE + n0] = c[mf][nf][0];
            smf[m0 * EPSTRIDE + n0 + 1] = c[mf][nf][1];
            smf[(m0 + 8) * EPSTRIDE + n0] = c[mf][nf][2];
            smf[(m0 + 8) * EPSTRIDE + n0 + 1] = c[mf][nf][3];
        }
}

// chunk loaders (per-chunk cp.async group)
__device__ __forceinline__ void gemm_load(uint32_t smb, int stage, const GemmSet& G,
                                          long long zA, long long zB, int bM, int bN, int j) {
    const int p = j >> 3, k0 = (j & 7) * 64;
    const bf16* Ap = ((p < 2) ? G.Ah : G.Al) + zA;
    const bf16* Bp = ((p == 1) ? G.Bl : G.Bh) + zB;
    uint32_t s0 = smb + stage * STAGE_BYTES;
    cp_tile(s0, Ap, D, bM, 1 << 30, k0);
    cp_tile(s0 + 16384, Bp, D, bN, 1 << 30, k0);
    cp_commit();
}
__device__ __forceinline__ void conv_load(uint32_t smb, int stage, const ConvSet& C,
                                          long long zH, int bM, int bN, int j) {
    const int p = j / 48, rr = j - p * 48;
    const int t = rr >> 4, k0 = (rr & 15) * 64;
    const bf16* Ap = ((p < 2) ? C.Wh : C.Wl) + (long long)t * C2 * C2;
    const bf16* Bp = ((p == 1) ? C.Hl : C.Hh) + zH;
    uint32_t s0 = smb + stage * STAGE_BYTES;
    cp_tile(s0, Ap, C2, bM, 1 << 30, k0);
    cp_tile(s0 + 16384, Bp, C2, bN + t - 1, D, k0);
    cp_commit();
}

// ---------------- merged split-bf16 GEMM: two problem sets via blockIdx.z ----------------
// EPI 0: fp32 natural ; EPI 1: bf16 hi/lo natural ; EPI 2: EPI1 + bf16 hi/lo transposed
template<int EPI>
__global__ __launch_bounds__(256, 2)
void mma_gemm(GemmPair P, long long sA, long long sB, int nc)
{
    extern __shared__ char sm[];
    const int tid = threadIdx.x, wid = tid >> 5, lane = tid & 31;
    const int bN = blockIdx.x * 128, bM = blockIdx.y * 128;
    const int z = blockIdx.z;
    const GemmSet G = P.s[z >> 4];
    const int zz = z & 15;
    const int wm = (wid >> 2) * 64, wn = (wid & 3) * 32;
    const uint32_t smb = s2u(sm);
    const long long zf = (long long)zz * D * D;
    const long long zA = zz * sA, zB = zz * sB;

    float c[4][4][4];
#pragma unroll
    for (int i = 0; i < 4; i++)
#pragma unroll
        for (int j = 0; j < 4; j++)
#pragma unroll
            for (int q = 0; q < 4; q++) c[i][j][q] = 0.f;

    gemm_load(smb, 0, G, zA, zB, bM, bN, 0);
    gemm_load(smb, 1, G, zA, zB, bM, bN, 1);

    for (int i = 0; i < nc; i++) {
        if (i < nc - 1) cp_wait<1>(); else cp_wait<0>();
        __syncthreads();
        if (i + 2 < nc) gemm_load(smb, (i + 2) % 3, G, zA, zB, bM, bN, i + 2);
        uint32_t s0 = smb + (i % 3) * STAGE_BYTES;
        compute_chunk(s0, s0 + 16384, wm, wn, lane, c);
    }
    __syncthreads();

    float* smf = (float*)sm;
    stage_acc(smf, wm, wn, lane, c);
    __syncthreads();

    const int r = tid >> 1, hf = tid & 1;
    if (EPI == 0) {
        float* dst = G.Fo + zf + (long long)(bM + r) * D + bN + hf * 64;
#pragma unroll
        for (int q = 0; q < 16; q++) {
            float4 v = *(float4*)&smf[r * EPSTRIDE + hf * 64 + q * 4];
            *(float4*)&dst[q * 4] = v;
        }
    } else {
        bf16* th = G.Th + zf + (long long)(bM + r) * D + bN + hf * 64;
        bf16* tl = G.Tl + zf + (long long)(bM + r) * D + bN + hf * 64;
#pragma unroll
        for (int q = 0; q < 32; q++) {
            float f0 = smf[r * EPSTRIDE + hf * 64 + q * 2];
            float f1 = smf[r * EPSTRIDE + hf * 64 + q * 2 + 1];
            bf16 h0, l0, h1, l1;
            split2(f0, h0, l0); split2(f1, h1, l1);
            __nv_bfloat162 vh; vh.x = h0; vh.y = h1;
            __nv_bfloat162 vl; vl.x = l0; vl.y = l1;
            *(__nv_bfloat162*)(th + q * 2) = vh;
            *(__nv_bfloat162*)(tl + q * 2) = vl;
        }
        if (EPI == 2) {
            const int n = tid >> 1, hm = tid & 1;
            bf16* uh = G.Uh + zf + (long long)(bN + n) * D + bM + hm * 64;
            bf16* ul = G.Ul + zf + (long long)(bN + n) * D + bM + hm * 64;
#pragma unroll
            for (int q = 0; q < 32; q++) {
                int m0 = hm * 64 + q * 2;
                float f0 = smf[m0 * EPSTRIDE + n];
                float f1 = smf[(m0 + 1) * EPSTRIDE + n];
                bf16 h0, l0, h1, l1;
                split2(f0, h0, l0); split2(f1, h1, l1);
                __nv_bfloat162 vh; vh.x = h0; vh.y = h1;
                __nv_bfloat162 vl; vl.x = l0; vl.y = l1;
                *(__nv_bfloat162*)(uh + q * 2) = vh;
                *(__nv_bfloat162*)(ul + q * 2) = vl;
            }
        }
    }
}

// ---------------- merged conv ----------------
__global__ __launch_bounds__(256, 2)
void mma_conv(ConvPair P, float* __restrict__ out)
{
    extern __shared__ char sm[];
    const int tid = threadIdx.x, wid = tid >> 5, lane = tid & 31;
    const int bN = blockIdx.x * 128, bM = blockIdx.y * 128;
    const int z = blockIdx.z;
    const ConvSet C = P.s[z >> 4];
    const int zz = z & 15;
    const int wm = (wid >> 2) * 64, wn = (wid & 3) * 32;
    const uint32_t smb = s2u(sm);
    const long long zH = (long long)zz * D * C2;

    float c[4][4][4];
#pragma unroll
    for (int i = 0; i < 4; i++)
#pragma unroll
        for (int j = 0; j < 4; j++)
#pragma unroll
            for (int q = 0; q < 4; q++) c[i][j][q] = 0.f;

    conv_load(smb, 0, C, zH, bM, bN, 0);
    conv_load(smb, 1, C, zH, bM, bN, 1);

    for (int i = 0; i < 144; i++) {
        if (i < 143) cp_wait<1>(); else cp_wait<0>();
        __syncthreads();
        if (i + 2 < 144) conv_load(smb, (i + 2) % 3, C, zH, bM, bN, i + 2);
        uint32_t s0 = smb + (i % 3) * STAGE_BYTES;
        compute_chunk(s0, s0 + 16384, wm, wn, lane, c);
    }
    __syncthreads();

    float* smf = (float*)sm;
    stage_acc(smf, wm, wn, lane, c);
    __syncthreads();

    const int r = tid >> 1, hf = tid & 1;
    const int o = bM + r;
    const float bo = __ldg(&C.bias[o]);
    float* dst = out + ((long long)zz * 2048 + C.chanOff + o) * D + bN + hf * 64;
#pragma unroll
    for (int q = 0; q < 16; q++) {
        float4 v = *(float4*)&smf[r * EPSTRIDE + hf * 64 + q * 4];
        v.x += bo; v.y += bo; v.z += bo; v.w += bo;
        *(float4*)&dst[q * 4] = v;
    }
}

// ---------------- aux kernels (merged pairs) ----------------
__global__ void conv_hl2(const float* __restrict__ a, bf16* __restrict__ ah, bf16* __restrict__ al,
                         const float* __restrict__ b, bf16* __restrict__ bh, bf16* __restrict__ bl)
{
    long long i = (long long)blockIdx.x * blockDim.x + threadIdx.x;
    if (i >= 2LL * FRM) return;
    const float* in = (i < FRM) ? a : b;
    bf16* oh = (i < FRM) ? ah : bh;
    bf16* ol = (i < FRM) ? al : bl;
    long long k = (i < FRM) ? i : i - FRM;
    bf16 h, l;
    split2(in[k], h, l);
    oh[k] = h; ol[k] = l;
}

struct TrArgs { const float* src[4]; bf16* dh[4]; bf16* dl[4]; };
__global__ void tr_w4(TrArgs A)
{
    __shared__ float t[32][33];
    const int j0 = blockIdx.x * 32, k0 = blockIdx.y * 32, w = blockIdx.z;
    const float* W = A.src[w];
    bf16* th = A.dh[w];
    bf16* tl = A.dl[w];
    const int tx = threadIdx.x, ty = threadIdx.y;
#pragma unroll
    for (int r = 0; r < 32; r += 8)
        t[ty + r][tx] = W[(long long)(k0 + ty + r) * D + j0 + tx];
    __syncthreads();
#pragma unroll
    for (int r = 0; r < 32; r += 8) {
        bf16 h, l;
        split2(t[tx][ty + r], h, l);
        long long o = (long long)(j0 + ty + r) * D + k0 + tx;
        th[o] = h; tl[o] = l;
    }
}

__global__ void g_stats2(const float* __restrict__ Gx, const float* __restrict__ Gs,
                         float* __restrict__ st)
{
    const int half = blockIdx.x >= BATCH * D;
    const int rowi = half ? blockIdx.x - BATCH * D : blockIdx.x;
    const float* row = (half ? Gs : Gx) + (long long)rowi * D;
    float* Mo = st + (half ? 2 : 0) * BATCH * D;
    float* Ro = st + (half ? 3 : 1) * BATCH * D;
    const int t = threadIdx.x, lane = t & 31, w = t >> 5;
    float v0 = row[t], v1 = row[t + 256];
    __shared__ float sh[8];
    float m = fmaxf(v0, v1);
#pragma unroll
    for (int o = 16; o > 0; o >>= 1) m = fmaxf(m, __shfl_xor_sync(~0u, m, o));
    if (lane == 0) sh[w] = m;
    __syncthreads();
    if (w == 0) {
        float x = (lane < 8) ? sh[lane] : -INFINITY;
#pragma unroll
        for (int o = 4; o > 0; o >>= 1) x = fmaxf(x, __shfl_xor_sync(~0u, x, o));
        if (lane == 0) sh[0] = x;
    }
    __syncthreads();
    const float M = sh[0];
    __syncthreads();
    float s = expf(v0 - M) + expf(v1 - M);
#pragma unroll
    for (int o = 16; o > 0; o >>= 1) s += __shfl_xor_sync(~0u, s, o);
    if (lane == 0) sh[w] = s;
    __syncthreads();
    if (w == 0) {
        float x = (lane < 8) ? sh[lane] : 0.f;
#pragma unroll
        for (int o = 4; o > 0; o >>= 1) x += __shfl_xor_sync(~0u, x, o);
        if (lane == 0) { Mo[rowi] = M; Ro[rowi] = 1.f / x; }
    }
}

__global__ void build_axt2(const float* __restrict__ Gx, const float* __restrict__ Gs,
                           const float* __restrict__ st,
                           bf16* __restrict__ xh, bf16* __restrict__ xl,
                           bf16* __restrict__ sh_, bf16* __restrict__ sl)
{
    long long gi = (long long)blockIdx.x * blockDim.x + threadIdx.x;
    if (gi >= 2LL * FRM) return;
    const int half = gi >= FRM;
    long long idx = half ? gi - FRM : gi;
    const float* G = half ? Gs : Gx;
    const float* Ms = st + (half ? 2 : 0) * BATCH * D;
    const float* Rs = st + (half ? 3 : 1) * BATCH * D;
    bf16* th = half ? sh_ : xh;
    bf16* tl = half ? sl : xl;
    int i = (int)(idx & (D - 1));
    long long z = idx >> 18;
    float v = expf(G[idx] - __ldg(&Ms[z * D + i])) * __ldg(&Rs[z * D + i]);
    bf16 h, l;
    split2(v, h, l);
    th[idx] = h; tl[idx] = l;
}

// Hat[z][h][c] = M[c][h]*In[c][h] (+pe) ; Hat[z][h][c+512] = In[c][h] (+pe)
__global__ void build_hatT2(const float* __restrict__ X, const float* __restrict__ Mx,
                            bf16* __restrict__ Hxh, bf16* __restrict__ Hxl,
                            const float* __restrict__ S, const float* __restrict__ Ms,
                            bf16* __restrict__ Hsh, bf16* __restrict__ Hsl)
{
    __shared__ float xs[32][33];
    __shared__ float ms[32][33];
    const int c0 = blockIdx.x * 32, h0 = blockIdx.y * 32;
    const int half = blockIdx.z >= BATCH;
    const int z = half ? blockIdx.z - BATCH : blockIdx.z;
    const float* In = half ? S : X;
    const float* Mm = half ? Ms : Mx;
    bf16* Hh = half ? Hsh : Hxh;
    bf16* Hl = half ? Hsl : Hxl;
    const int addPos = half;
    const int tx = threadIdx.x, ty = threadIdx.y;
    const long long zf = (long long)z * D * D;
    const long long zh = (long long)z * D * C2;
#pragma unroll
    for (int r = 0; r < 32; r += 8) {
        xs[ty + r][tx] = In[zf + (long long)(c0 + ty + r) * D + h0 + tx];
        ms[ty + r][tx] = Mm[zf + (long long)(c0 + ty + r) * D + h0 + tx];
    }
    __syncthreads();
#pragma unroll
    for (int r = 0; r < 32; r += 8) {
        const int h = h0 + ty + r, c = c0 + tx;
        const float pe = addPos ? sinf((float)h) : 0.f;
        const float xv = xs[tx][ty + r];
        const float mv = ms[tx][ty + r];
        bf16 hh, ll;
        long long o = zh + (long long)h * C2 + c;
        split2(mv * xv + pe, hh, ll);
        Hh[o] = hh; Hl[o] = ll;
        split2(xv + pe, hh, ll);
        Hh[o + D] = hh; Hl[o + D] = ll;
    }
}

__global__ void pack_w_hl2(const float* __restrict__ wx, bf16* __restrict__ xh, bf16* __restrict__ xl,
                           const float* __restrict__ ws, bf16* __restrict__ sh_, bf16* __restrict__ sl)
{
    long long gi = (long long)blockIdx.x * blockDim.x + threadIdx.x;
    if (gi >= 2LL * WKN) return;
    const int half = gi >= WKN;
    long long idx = half ? gi - WKN : gi;
    const float* w = half ? ws : wx;
    bf16* wh = half ? sh_ : xh;
    bf16* wl = half ? sl : xl;
    int i = (int)(idx & (C2 - 1));
    int o = (int)((idx >> 10) & (C2 - 1));
    int t = (int)(idx >> 20);
    bf16 h, l;
    split2(w[(long long)o * 9216 + (long long)i * 9 + t * 3 + 1], h, l);
    wh[idx] = h; wl[idx] = l;
}

// ---------------- launcher ----------------
extern "C" void kernel_launch(void* const* d_in, const int* in_sizes, int n_in,
                              void* d_out, int out_size)
{
    const float* X   = (const float*)d_in[0];
    const float* S   = (const float*)d_in[1];
    const float* W1x = (const float*)d_in[2];
    const float* W1s = (const float*)d_in[3];
    const float* W2x = (const float*)d_in[4];
    const float* W2s = (const float*)d_in[5];
    const float* cwx = (const float*)d_in[6];
    const float* cbx = (const float*)d_in[7];
    const float* cws = (const float*)d_in[8];
    const float* cbs = (const float*)d_in[9];
    float* out = (float*)d_out;

    bf16 *Xsp, *Ssp, *W1xT, *W1sT, *W2xT, *W2sT, *Xe, *XeT, *Se, *SeT;
    bf16 *AxT, *AsT, *Xa, *Sa, *Hx, *Hs, *Wkx, *Wks;
    float *Gx, *Gs, *st, *Mx, *Ms;
    cudaGetSymbolAddress((void**)&Xsp, g_Xsp);   cudaGetSymbolAddress((void**)&Ssp, g_Ssp);
    cudaGetSymbolAddress((void**)&W1xT, g_W1xT); cudaGetSymbolAddress((void**)&W1sT, g_W1sT);
    cudaGetSymbolAddress((void**)&W2xT, g_W2xT); cudaGetSymbolAddress((void**)&W2sT, g_W2sT);
    cudaGetSymbolAddress((void**)&Xe, g_Xe);     cudaGetSymbolAddress((void**)&XeT, g_XeT);
    cudaGetSymbolAddress((void**)&Se, g_Se);     cudaGetSymbolAddress((void**)&SeT, g_SeT);
    cudaGetSymbolAddress((void**)&Gx, g_Gx);     cudaGetSymbolAddress((void**)&Gs, g_Gs);
    cudaGetSymbolAddress((void**)&st, g_st);
    cudaGetSymbolAddress((void**)&AxT, g_AxT);   cudaGetSymbolAddress((void**)&AsT, g_AsT);
    cudaGetSymbolAddress((void**)&Xa, g_Xa);     cudaGetSymbolAddress((void**)&Sa, g_Sa);
    cudaGetSymbolAddress((void**)&Mx, g_Mx);     cudaGetSymbolAddress((void**)&Ms, g_Ms);
    cudaGetSymbolAddress((void**)&Hx, g_Hx);     cudaGetSymbolAddress((void**)&Hs, g_Hs);
    cudaGetSymbolAddress((void**)&Wkx, g_Wkx);   cudaGetSymbolAddress((void**)&Wks, g_Wks);

    cudaFuncSetAttribute(mma_gemm<0>, cudaFuncAttributeMaxDynamicSharedMemorySize, SM_DYN);
    cudaFuncSetAttribute(mma_gemm<1>, cudaFuncAttributeMaxDynamicSharedMemorySize, SM_DYN);
    cudaFuncSetAttribute(mma_gemm<2>, cudaFuncAttributeMaxDynamicSharedMemorySize, SM_DYN);
    cudaFuncSetAttribute(mma_conv,    cudaFuncAttributeMaxDynamicSharedMemorySize, SM_DYN);

    const long long sF = (long long)D * D;
    const long long wofs = (long long)D * D;
    const long long fofs = (long long)FRM;
    const long long hofs = (long long)HATN;
    const long long kofs = (long long)WKN;
    const dim3 gG(4, 4, 32);
    const dim3 gC(4, 8, 32);

    // prep (merged)
    {
        TrArgs ta;
        ta.src[0] = W1x; ta.dh[0] = W1xT; ta.dl[0] = W1xT + wofs;
        ta.src[1] = W1s; ta.dh[1] = W1sT; ta.dl[1] = W1sT + wofs;
        ta.src[2] = W2x; ta.dh[2] = W2xT; ta.dl[2] = W2xT + wofs;
        ta.src[3] = W2s; ta.dh[3] = W2sT; ta.dl[3] = W2sT + wofs;
        tr_w4<<<dim3(16, 16, 4), dim3(32, 8)>>>(ta);
    }
    conv_hl2<<<(int)((2LL * FRM + 255) / 256), 256>>>(X, Xsp, Xsp + fofs, S, Ssp, Ssp + fofs);
    pack_w_hl2<<<(int)((2LL * WKN + 255) / 256), 256>>>(cwx, Wkx, Wkx + kofs, cws, Wks, Wks + kofs);

    // projections (cross-wired): Xe = S@W1x, Se = X@W1s
    {
        GemmPair P;
        P.s[0] = { Ssp, Ssp + fofs, W1xT, W1xT + wofs, nullptr, Xe, Xe + fofs, XeT, XeT + fofs };
        P.s[1] = { Xsp, Xsp + fofs, W1sT, W1sT + wofs, nullptr, Se, Se + fofs, SeT, SeT + fofs };
        mma_gemm<2><<<gG, 256, SM_DYN>>>(P, sF, 0, 24);
    }
    // Gram (single-pass hi*hi): G[i][j] = sum_l XeT[i][l]*XeT[j][l]
    {
        GemmPair P;
        P.s[0] = { XeT, XeT + fofs, XeT, XeT + fofs, Gx, nullptr, nullptr, nullptr, nullptr };
        P.s[1] = { SeT, SeT + fofs, SeT, SeT + fofs, Gs, nullptr, nullptr, nullptr, nullptr };
        mma_gemm<0><<<gG, 256, SM_DYN>>>(P, sF, sF, 8);
    }
    // softmax stats + transposed attention matrices
    g_stats2<<<2 * BATCH * D, 256>>>(Gx, Gs, st);
    build_axt2<<<(int)((2LL * FRM + 255) / 256), 256>>>(Gx, Gs, st, AxT, AxT + fofs, AsT, AsT + fofs);
    // apply: Xa[l][j] = sum_i Xe[l][i]*AxT[j][i]
    {
        GemmPair P;
        P.s[0] = { Xe, Xe + fofs, AxT, AxT + fofs, nullptr, Xa, Xa + fofs, nullptr, nullptr };
        P.s[1] = { Se, Se + fofs, AsT, AsT + fofs, nullptr, Sa, Sa + fofs, nullptr, nullptr };
        mma_gemm<1><<<gG, 256, SM_DYN>>>(P, sF, sF, 24);
    }
    // mix: Mx[l][j] = sum_k Xa[l][k]*W2xT[j][k]
    {
        GemmPair P;
        P.s[0] = { Xa, Xa + fofs, W2xT, W2xT + wofs, Mx, nullptr, nullptr, nullptr, nullptr };
        P.s[1] = { Sa, Sa + fofs, W2sT, W2sT + wofs, Ms, nullptr, nullptr, nullptr, nullptr };
        mma_gemm<0><<<gG, 256, SM_DYN>>>(P, sF, 0, 24);
    }
    // conv inputs + convs
    build_hatT2<<<dim3(16, 16, 32), dim3(32, 8)>>>(X, Mx, Hx, Hx + hofs, S, Ms, Hs, Hs + hofs);
    {
        ConvPair P;
        P.s[0] = { Hx, Hx + hofs, Wkx, Wkx + kofs, cbx, 0 };
        P.s[1] = { Hs, Hs + hofs, Wks, Wks + kofs, cbs, C2 };
        mma_conv<<<gC, 256, SM_DYN>>>(P, out);
    }
}